// round 9
// baseline (speedup 1.0000x reference)
#include <cuda_runtime.h>
#include <math.h>
#include <stdint.h>

#define N_NODES 100000
#define NFEAT   256
#define HID     32
#define NCOL    64
#define TILE_M  128
#define NT      782          // ceil(100000/128)

// smem: fragment-packed tf32 B [16 ks][8 nt][32 lane][4 f32] = 65536 B
#define BFRAG_OFF 0
#define BIAS_OFF  65536
#define WLIN_OFF  (BIAS_OFF + 256)
#define BLIN_OFF  (WLIN_OFF + 128)
#define SMEM_TOTAL (BLIN_OFF + 16)     // 65952 B -> 3 CTAs/SM

// persistent device scratch
__device__ float g_Bfrag[NCOL * NFEAT];   // tf32-rounded, fragment-packed
__device__ float g_bias[NCOL];
__device__ float g_wlin[HID];
__device__ float g_blin;

__global__ void prep_kernel(const float* __restrict__ Wz, const float* __restrict__ bz,
                            const float* __restrict__ Wh, const float* __restrict__ bh,
                            const float* __restrict__ Wlin, const float* __restrict__ blin)
{
    int idx = blockIdx.x * blockDim.x + threadIdx.x;
    if (idx < NCOL * NFEAT) {
        int n = idx / NFEAT, k = idx % NFEAT;     // k = PHYSICAL column of x
        const float* W = (n < HID) ? Wz : Wh;     // (2,1,288,32) row-major
        int nn = n & (HID - 1);
        float w = W[k * HID + nn] + W[288 * HID + k * HID + nn];
        uint32_t tf;
        asm("cvt.rna.tf32.f32 %0, %1;" : "=r"(tf) : "f"(w));
        // fragment packing: ks = k>>4; lane = (n&7)*4 + ((k>>2)&3); slot j = k&3
        int ks = k >> 4, nt = n >> 3;
        int lane = (n & 7) * 4 + ((k >> 2) & 3);
        int off = (((ks * 8 + nt) * 32) + lane) * 4 + (k & 3);
        g_Bfrag[off] = __uint_as_float(tf);
    }
    if (blockIdx.x == 0) {
        int t = threadIdx.x;
        if (t < NCOL) g_bias[t] = (t < HID) ? bz[t] : bh[t - HID];
        if (t < HID)  g_wlin[t] = Wlin[t];
        if (t == 0)   g_blin = blin[0];
    }
}

// ---------- helpers ----------
#define MMAT(acc, a0, a1, a2, a3, b0, b1) \
    asm("mma.sync.aligned.m16n8k8.row.col.f32.tf32.tf32.f32 " \
        "{%0,%1,%2,%3}, {%4,%5,%6,%7}, {%8,%9}, {%0,%1,%2,%3};" \
        : "+f"((acc)[0]), "+f"((acc)[1]), "+f"((acc)[2]), "+f"((acc)[3]) \
        : "r"(a0), "r"(a1), "r"(a2), "r"(a3), "r"(b0), "r"(b1))

#define CVT_TF32(d, f) asm("cvt.rna.tf32.f32 %0, %1;" : "=r"(d) : "f"(f))

#define LDS128(v, addr) \
    asm("ld.shared.v4.b32 {%0,%1,%2,%3}, [%4];" \
        : "=r"((v).x), "=r"((v).y), "=r"((v).z), "=r"((v).w) : "r"(addr))

__device__ __forceinline__ float fast_tanh(float v) {
    return 1.0f - 2.0f / (__expf(2.0f * v) + 1.0f);
}

extern __shared__ __align__(128) char smem[];

__global__ __launch_bounds__(256, 3)
void gcn_tf32_kernel(const float* __restrict__ x, float* __restrict__ out)
{
    const int tid  = threadIdx.x;
    const uint32_t sbase = (uint32_t)__cvta_generic_to_shared(smem);

    // ---- stage packed B (linear uint4 copy, 4096 quads) ----
    {
        const uint4* src = reinterpret_cast<const uint4*>(g_Bfrag);
#pragma unroll
        for (int i = 0; i < 16; i++) {
            int idx = tid + i * 256;
            reinterpret_cast<uint4*>(smem + BFRAG_OFF)[idx] = src[idx];
        }
    }
    if (tid < NCOL) reinterpret_cast<float*>(smem + BIAS_OFF)[tid] = g_bias[tid];
    if (tid < HID)  reinterpret_cast<float*>(smem + WLIN_OFF)[tid] = g_wlin[tid];
    if (tid == 0)   reinterpret_cast<float*>(smem + BLIN_OFF)[0] = g_blin;
    __syncthreads();

    const int warp = tid >> 5, lane = tid & 31;
    const int g = lane >> 2, t = lane & 3;

    const int nodeBase = blockIdx.x * TILE_M + warp * 16;
    const int r0 = nodeBase + g, r1 = r0 + 8;
    const int cr0 = (r0 < N_NODES) ? r0 : (N_NODES - 1);
    const int cr1 = (r1 < N_NODES) ? r1 : (N_NODES - 1);
    const float4* p0 = reinterpret_cast<const float4*>(x) + (size_t)cr0 * 64 + t;
    const float4* p1 = reinterpret_cast<const float4*>(x) + (size_t)cr1 * 64 + t;

    const uint32_t blane = sbase + BFRAG_OFF + lane * 16;

    float acc[8][4];
#pragma unroll
    for (int i = 0; i < 8; i++)
#pragma unroll
        for (int j = 0; j < 4; j++) acc[i][j] = 0.0f;

#pragma unroll 2
    for (int ks = 0; ks < 16; ks++) {
        float4 v0 = __ldg(p0 + ks * 4);   // row r0, physical cols 4t..4t+3
        float4 v1 = __ldg(p1 + ks * 4);   // row r1

        uint32_t a[8];
        CVT_TF32(a[0], v0.x); CVT_TF32(a[1], v1.x);
        CVT_TF32(a[2], v0.y); CVT_TF32(a[3], v1.y);
        CVT_TF32(a[4], v0.z); CVT_TF32(a[5], v1.z);
        CVT_TF32(a[6], v0.w); CVT_TF32(a[7], v1.w);

        uint4 b[8];
#pragma unroll
        for (int nt = 0; nt < 8; nt++)
            LDS128(b[nt], blane + (ks * 8 + nt) * 512);

        // pass 1: k8 block 0 (cols 4t, 4t+1 == logical t, t+4)
#pragma unroll
        for (int nt = 0; nt < 8; nt++)
            MMAT(acc[nt], a[0], a[1], a[2], a[3], b[nt].x, b[nt].y);
        // pass 2: k8 block 1 (cols 4t+2, 4t+3 == logical t+8, t+12)
#pragma unroll
        for (int nt = 0; nt < 8; nt++)
            MMAT(acc[nt], a[4], a[5], a[6], a[7], b[nt].z, b[nt].w);
    }

    // ---- epilogue: register/shuffle based ----
    const float* sBias = reinterpret_cast<const float*>(smem + BIAS_OFF);
    const float* sWlin = reinterpret_cast<const float*>(smem + WLIN_OFF);
    const float  blin  = reinterpret_cast<const float*>(smem + BLIN_OFF)[0];

#pragma unroll
    for (int row = 0; row < 2; row++) {
        float s = 0.0f;
#pragma unroll
        for (int nt = 0; nt < 4; nt++) {
#pragma unroll
            for (int j = 0; j < 2; j++) {
                int c = nt * 8 + 2 * t + j;
                float zv = acc[nt][row * 2 + j]     + sBias[c];
                float hv = acc[nt + 4][row * 2 + j] + sBias[HID + c];
                float z  = 1.0f / (1.0f + __expf(-zv));
                float th = fast_tanh(hv);
                float h  = fmaxf((1.0f - z) * th, 0.0f);
                s = fmaf(h, sWlin[c], s);
            }
        }
        s += __shfl_xor_sync(0xffffffffu, s, 1);
        s += __shfl_xor_sync(0xffffffffu, s, 2);
        int node = row ? r1 : r0;
        if (t == 0 && node < N_NODES) out[node] = s + blin;
    }
}

extern "C" void kernel_launch(void* const* d_in, const int* in_sizes, int n_in,
                              void* d_out, int out_size)
{
    const float* x    = (const float*)d_in[0];
    const float* Wz   = (const float*)d_in[3];
    const float* bz   = (const float*)d_in[4];
    const float* Wh   = (const float*)d_in[7];
    const float* bh   = (const float*)d_in[8];
    const float* Wlin = (const float*)d_in[9];
    const float* blin = (const float*)d_in[10];
    float* out = (float*)d_out;

    prep_kernel<<<64, 256>>>(Wz, bz, Wh, bh, Wlin, blin);

    cudaFuncSetAttribute(gcn_tf32_kernel,
                         cudaFuncAttributeMaxDynamicSharedMemorySize, SMEM_TOTAL);
    gcn_tf32_kernel<<<NT, 256, SMEM_TOTAL>>>(x, out);
}

// round 10
// speedup vs baseline: 1.1204x; 1.1204x over previous
#include <cuda_runtime.h>
#include <cuda_bf16.h>
#include <math.h>
#include <stdint.h>

#define N_NODES 100000
#define NFEAT   256
#define HID     32
#define NCOL    64
#define TILE_M  256
#define NT      391          // ceil(100000/256)

// B smem: 64 rows x 264 bf16 (528B padded rows, conflict-free ldmatrix phases)
#define BROW_B   528
#define B_BYTES  (NCOL * BROW_B)     // 33792
#define B_HI_OFF 0
#define B_LO_OFF B_BYTES
#define BIAS_OFF (2 * B_BYTES)             // 64 f32
#define WLIN_OFF (BIAS_OFF + 256)          // 32 f32
#define BLIN_OFF (WLIN_OFF + 128)
#define SMEM_TOTAL (BLIN_OFF + 16)         // ~67.9 KB

// persistent device scratch (prep output; W stored K-PERMUTED within 16-blocks)
__device__ __nv_bfloat16 g_Whi[NCOL * NFEAT];
__device__ __nv_bfloat16 g_Wlo[NCOL * NFEAT];
__device__ float g_bias[NCOL];
__device__ float g_wlin[HID];
__device__ float g_blin;

// logical fragment position p -> physical k within a 16-block, so that lane t's
// float4 at physical cols 4t..4t+3 lands at logical (2t,2t+1,2t+8,2t+9)
__device__ __forceinline__ int kperm(int p) {
    return (p < 8) ? (4 * (p >> 1) + (p & 1))
                   : (4 * ((p - 8) >> 1) + 2 + (p & 1));
}

__global__ void prep_kernel(const float* __restrict__ Wz, const float* __restrict__ bz,
                            const float* __restrict__ Wh, const float* __restrict__ bh,
                            const float* __restrict__ Wlin, const float* __restrict__ blin)
{
    int idx = blockIdx.x * blockDim.x + threadIdx.x;
    if (idx < NCOL * NFEAT) {
        int n = idx / NFEAT, k = idx % NFEAT;               // k = logical position
        int kp = (k & ~15) | kperm(k & 15);                 // physical source col
        const float* W = (n < HID) ? Wz : Wh;               // (2,1,288,32) row-major
        int nn = n & (HID - 1);
        float w = W[kp * HID + nn] + W[288 * HID + kp * HID + nn];
        __nv_bfloat16 hi = __float2bfloat16(w);
        g_Whi[idx] = hi;
        g_Wlo[idx] = __float2bfloat16(w - __bfloat162float(hi));
    }
    if (blockIdx.x == 0) {
        int t = threadIdx.x;
        if (t < NCOL) g_bias[t] = (t < HID) ? bz[t] : bh[t - HID];
        if (t < HID)  g_wlin[t] = Wlin[t];
        if (t == 0)   g_blin = blin[0];
    }
}

// ---------- helpers ----------
#define MMA(acc, a, b0, b1) \
    asm("mma.sync.aligned.m16n8k16.row.col.f32.bf16.bf16.f32 " \
        "{%0,%1,%2,%3}, {%4,%5,%6,%7}, {%8,%9}, {%0,%1,%2,%3};" \
        : "+f"((acc)[0]), "+f"((acc)[1]), "+f"((acc)[2]), "+f"((acc)[3]) \
        : "r"((a)[0]), "r"((a)[1]), "r"((a)[2]), "r"((a)[3]), "r"(b0), "r"(b1))

#define LDM4(r, addr) \
    asm("ldmatrix.sync.aligned.m8n8.x4.shared.b16 {%0,%1,%2,%3}, [%4];" \
        : "=r"((r)[0]), "=r"((r)[1]), "=r"((r)[2]), "=r"((r)[3]) : "r"(addr))

// pack (fx,fy) -> bf16x2 hi (exact round) and bf16x2 of residual
#define CVTHILO2(fx, fy, h, l) do { \
    asm("cvt.rn.bf16x2.f32 %0, %1, %2;" : "=r"(h) : "f"(fy), "f"(fx)); \
    float _rx = (fx) - __uint_as_float((h) << 16); \
    float _ry = (fy) - __uint_as_float((h) & 0xffff0000u); \
    asm("cvt.rn.bf16x2.f32 %0, %1, %2;" : "=r"(l) : "f"(_ry), "f"(_rx)); \
} while (0)

__device__ __forceinline__ float fast_tanh(float v) {
    return 1.0f - 2.0f / (__expf(2.0f * v) + 1.0f);
}

extern __shared__ __align__(128) char smem[];

__global__ __launch_bounds__(256, 2)
void gcn_hmma_kernel(const float* __restrict__ x, float* __restrict__ out)
{
    const int tid  = threadIdx.x;
    const uint32_t sbase = (uint32_t)__cvta_generic_to_shared(smem);

    // ---- stage B hi/lo into padded smem rows (8B chunks) ----
    {
        const uint2* whi = reinterpret_cast<const uint2*>(g_Whi);
        const uint2* wlo = reinterpret_cast<const uint2*>(g_Wlo);
#pragma unroll
        for (int i = 0; i < 16; i++) {
            int idx = tid + i * 256;          // 0..4095
            int n = idx >> 6, c = idx & 63;   // 64 chunks of 4 bf16 per row
            *reinterpret_cast<uint2*>(smem + B_HI_OFF + n * BROW_B + c * 8) = whi[idx];
            *reinterpret_cast<uint2*>(smem + B_LO_OFF + n * BROW_B + c * 8) = wlo[idx];
        }
    }
    if (tid < NCOL) reinterpret_cast<float*>(smem + BIAS_OFF)[tid] = g_bias[tid];
    if (tid < HID)  reinterpret_cast<float*>(smem + WLIN_OFF)[tid] = g_wlin[tid];
    if (tid == 0)   reinterpret_cast<float*>(smem + BLIN_OFF)[0] = g_blin;
    __syncthreads();

    const int warp = tid >> 5, lane = tid & 31;
    const int g = lane >> 2, t = lane & 3;

    // 32 rows per warp: two 16-row A-fragment sets
    const int nodeBase = blockIdx.x * TILE_M + warp * 32;
    int rows[4];
    rows[0] = nodeBase + g;        // set0 lo
    rows[1] = nodeBase + 8 + g;    // set0 hi
    rows[2] = nodeBase + 16 + g;   // set1 lo
    rows[3] = nodeBase + 24 + g;   // set1 hi
    const float4* p[4];
#pragma unroll
    for (int i = 0; i < 4; i++) {
        int cr = (rows[i] < N_NODES) ? rows[i] : (N_NODES - 1);
        p[i] = reinterpret_cast<const float4*>(x) + (size_t)cr * 64 + t;
    }

    // ldmatrix per-lane address (logical layout; matches permuted-stored W)
    const int lm_n = ((lane >> 4) & 1) * 8 + (lane & 7);
    const int lm_k = ((lane >> 3) & 1) * 8;
    const uint32_t lmhi = sbase + lm_n * BROW_B + lm_k * 2;

    float acc[2][8][4];
#pragma unroll
    for (int s = 0; s < 2; s++)
#pragma unroll
        for (int i = 0; i < 8; i++)
#pragma unroll
            for (int j = 0; j < 4; j++) acc[s][i][j] = 0.0f;

    for (int ks = 0; ks < 16; ks++) {
        float4 v0 = __ldg(p[0] + ks * 4);
        float4 v1 = __ldg(p[1] + ks * 4);
        float4 v2 = __ldg(p[2] + ks * 4);
        float4 v3 = __ldg(p[3] + ks * 4);

        uint32_t ah[2][4], al[2][4];
        CVTHILO2(v0.x, v0.y, ah[0][0], al[0][0]);
        CVTHILO2(v1.x, v1.y, ah[0][1], al[0][1]);
        CVTHILO2(v0.z, v0.w, ah[0][2], al[0][2]);
        CVTHILO2(v1.z, v1.w, ah[0][3], al[0][3]);
        CVTHILO2(v2.x, v2.y, ah[1][0], al[1][0]);
        CVTHILO2(v3.x, v3.y, ah[1][1], al[1][1]);
        CVTHILO2(v2.z, v2.w, ah[1][2], al[1][2]);
        CVTHILO2(v3.z, v3.w, ah[1][3], al[1][3]);

        uint32_t bh[4][4];
#pragma unroll
        for (int nt2 = 0; nt2 < 4; nt2++)
            LDM4(bh[nt2], lmhi + nt2 * (16 * BROW_B) + ks * 32);

        // pass 1: hi*hi — 16 independent accumulators back to back
#pragma unroll
        for (int nt2 = 0; nt2 < 4; nt2++) {
#pragma unroll
            for (int s = 0; s < 2; s++) {
                MMA(acc[s][2 * nt2],     ah[s], bh[nt2][0], bh[nt2][1]);
                MMA(acc[s][2 * nt2 + 1], ah[s], bh[nt2][2], bh[nt2][3]);
            }
        }
        // pass 2: lo*hi (reuse bh)
#pragma unroll
        for (int nt2 = 0; nt2 < 4; nt2++) {
#pragma unroll
            for (int s = 0; s < 2; s++) {
                MMA(acc[s][2 * nt2],     al[s], bh[nt2][0], bh[nt2][1]);
                MMA(acc[s][2 * nt2 + 1], al[s], bh[nt2][2], bh[nt2][3]);
            }
        }
        // pass 3: hi*lo
#pragma unroll
        for (int nt2 = 0; nt2 < 4; nt2++) {
            uint32_t bl[4];
            LDM4(bl, lmhi + B_BYTES + nt2 * (16 * BROW_B) + ks * 32);
#pragma unroll
            for (int s = 0; s < 2; s++) {
                MMA(acc[s][2 * nt2],     ah[s], bl[0], bl[1]);
                MMA(acc[s][2 * nt2 + 1], ah[s], bl[2], bl[3]);
            }
        }
    }

    // ---- epilogue: fully register/shuffle based ----
    const float* sBias = reinterpret_cast<const float*>(smem + BIAS_OFF);
    const float* sWlin = reinterpret_cast<const float*>(smem + WLIN_OFF);
    const float  blin  = reinterpret_cast<const float*>(smem + BLIN_OFF)[0];

#pragma unroll
    for (int s = 0; s < 2; s++) {
#pragma unroll
        for (int row = 0; row < 2; row++) {
            float sum = 0.0f;
#pragma unroll
            for (int nt = 0; nt < 4; nt++) {
#pragma unroll
                for (int j = 0; j < 2; j++) {
                    int c = nt * 8 + 2 * t + j;
                    float zv = acc[s][nt][row * 2 + j]     + sBias[c];
                    float hv = acc[s][nt + 4][row * 2 + j] + sBias[HID + c];
                    float z  = 1.0f / (1.0f + __expf(-zv));
                    float th = fast_tanh(hv);
                    float h  = fmaxf((1.0f - z) * th, 0.0f);
                    sum = fmaf(h, sWlin[c], sum);
                }
            }
            sum += __shfl_xor_sync(0xffffffffu, sum, 1);
            sum += __shfl_xor_sync(0xffffffffu, sum, 2);
            int node = rows[s * 2 + row];
            if (t == 0 && node < N_NODES) out[node] = sum + blin;
        }
    }
}

extern "C" void kernel_launch(void* const* d_in, const int* in_sizes, int n_in,
                              void* d_out, int out_size)
{
    const float* x    = (const float*)d_in[0];
    const float* Wz   = (const float*)d_in[3];
    const float* bz   = (const float*)d_in[4];
    const float* Wh   = (const float*)d_in[7];
    const float* bh   = (const float*)d_in[8];
    const float* Wlin = (const float*)d_in[9];
    const float* blin = (const float*)d_in[10];
    float* out = (float*)d_out;

    prep_kernel<<<64, 256>>>(Wz, bz, Wh, bh, Wlin, blin);

    cudaFuncSetAttribute(gcn_hmma_kernel,
                         cudaFuncAttributeMaxDynamicSharedMemorySize, SMEM_TOTAL);
    gcn_hmma_kernel<<<NT, 256, SMEM_TOTAL>>>(x, out);
}

// round 11
// speedup vs baseline: 1.2187x; 1.0878x over previous
#include <cuda_runtime.h>
#include <cuda_bf16.h>
#include <math.h>
#include <stdint.h>

#define N_NODES 100000
#define NFEAT   256
#define HID     32
#define NCOL    64
#define TILE_M  128
#define NT      782          // ceil(100000/128)

// B smem: 64 rows x 264 bf16 (528B padded rows, conflict-free ldmatrix phases)
#define BROW_B   528
#define B_BYTES  (NCOL * BROW_B)     // 33792
#define B_HI_OFF 0
#define B_LO_OFF B_BYTES
#define BIAS_OFF (2 * B_BYTES)             // 64 f32
#define WLIN_OFF (BIAS_OFF + 256)          // 32 f32
#define BLIN_OFF (WLIN_OFF + 128)
#define SMEM_TOTAL (BLIN_OFF + 16)         // ~67.9 KB

// persistent device scratch (prep output; W stored K-PERMUTED within 16-blocks)
__device__ __nv_bfloat16 g_Whi[NCOL * NFEAT];
__device__ __nv_bfloat16 g_Wlo[NCOL * NFEAT];
__device__ float g_bias[NCOL];
__device__ float g_wlin[HID];
__device__ float g_blin;

// logical fragment position p -> physical k within a 16-block, so that lane t's
// float4 at physical cols 4t..4t+3 lands at logical (2t,2t+1,2t+8,2t+9)
__device__ __forceinline__ int kperm(int p) {
    return (p < 8) ? (4 * (p >> 1) + (p & 1))
                   : (4 * ((p - 8) >> 1) + 2 + (p & 1));
}

__global__ void prep_kernel(const float* __restrict__ Wz, const float* __restrict__ bz,
                            const float* __restrict__ Wh, const float* __restrict__ bh,
                            const float* __restrict__ Wlin, const float* __restrict__ blin)
{
    int idx = blockIdx.x * blockDim.x + threadIdx.x;
    if (idx < NCOL * NFEAT) {
        int n = idx / NFEAT, k = idx % NFEAT;               // k = logical position
        int kp = (k & ~15) | kperm(k & 15);                 // physical source col
        const float* W = (n < HID) ? Wz : Wh;               // (2,1,288,32) row-major
        int nn = n & (HID - 1);
        float w = W[kp * HID + nn] + W[288 * HID + kp * HID + nn];
        __nv_bfloat16 hi = __float2bfloat16(w);
        g_Whi[idx] = hi;
        g_Wlo[idx] = __float2bfloat16(w - __bfloat162float(hi));
    }
    if (blockIdx.x == 0) {
        int t = threadIdx.x;
        if (t < NCOL) g_bias[t] = (t < HID) ? bz[t] : bh[t - HID];
        if (t < HID)  g_wlin[t] = Wlin[t];
        if (t == 0)   g_blin = blin[0];
    }
}

// ---------- helpers ----------
#define MMA(acc, a, b0, b1) \
    asm("mma.sync.aligned.m16n8k16.row.col.f32.bf16.bf16.f32 " \
        "{%0,%1,%2,%3}, {%4,%5,%6,%7}, {%8,%9}, {%0,%1,%2,%3};" \
        : "+f"((acc)[0]), "+f"((acc)[1]), "+f"((acc)[2]), "+f"((acc)[3]) \
        : "r"((a)[0]), "r"((a)[1]), "r"((a)[2]), "r"((a)[3]), "r"(b0), "r"(b1))

#define LDM4(r, addr) \
    asm("ldmatrix.sync.aligned.m8n8.x4.shared.b16 {%0,%1,%2,%3}, [%4];" \
        : "=r"((r)[0]), "=r"((r)[1]), "=r"((r)[2]), "=r"((r)[3]) : "r"(addr))

// pack (fx,fy) -> bf16x2 hi (exact round) and bf16x2 of residual
#define CVTHILO2(fx, fy, h, l) do { \
    asm("cvt.rn.bf16x2.f32 %0, %1, %2;" : "=r"(h) : "f"(fy), "f"(fx)); \
    float _rx = (fx) - __uint_as_float((h) << 16); \
    float _ry = (fy) - __uint_as_float((h) & 0xffff0000u); \
    asm("cvt.rn.bf16x2.f32 %0, %1, %2;" : "=r"(l) : "f"(_ry), "f"(_rx)); \
} while (0)

__device__ __forceinline__ float fast_tanh(float v) {
    return 1.0f - 2.0f / (__expf(2.0f * v) + 1.0f);
}

extern __shared__ __align__(128) char smem[];

__global__ __launch_bounds__(256, 3)
void gcn_hmma_kernel(const float* __restrict__ x, float* __restrict__ out)
{
    const int tid  = threadIdx.x;
    const uint32_t sbase = (uint32_t)__cvta_generic_to_shared(smem);

    // ---- stage B hi/lo into padded smem rows (8B chunks) ----
    {
        const uint2* whi = reinterpret_cast<const uint2*>(g_Whi);
        const uint2* wlo = reinterpret_cast<const uint2*>(g_Wlo);
#pragma unroll
        for (int i = 0; i < 16; i++) {
            int idx = tid + i * 256;          // 0..4095
            int n = idx >> 6, c = idx & 63;   // 64 chunks of 4 bf16 per row
            *reinterpret_cast<uint2*>(smem + B_HI_OFF + n * BROW_B + c * 8) = whi[idx];
            *reinterpret_cast<uint2*>(smem + B_LO_OFF + n * BROW_B + c * 8) = wlo[idx];
        }
    }
    if (tid < NCOL) reinterpret_cast<float*>(smem + BIAS_OFF)[tid] = g_bias[tid];
    if (tid < HID)  reinterpret_cast<float*>(smem + WLIN_OFF)[tid] = g_wlin[tid];
    if (tid == 0)   reinterpret_cast<float*>(smem + BLIN_OFF)[0] = g_blin;
    __syncthreads();

    const int warp = tid >> 5, lane = tid & 31;
    const int g = lane >> 2, t = lane & 3;

    const int nodeBase = blockIdx.x * TILE_M + warp * 16;
    const int r0 = nodeBase + g, r1 = r0 + 8;
    const int cr0 = (r0 < N_NODES) ? r0 : (N_NODES - 1);
    const int cr1 = (r1 < N_NODES) ? r1 : (N_NODES - 1);
    const float4* p0 = reinterpret_cast<const float4*>(x) + (size_t)cr0 * 64 + t;
    const float4* p1 = reinterpret_cast<const float4*>(x) + (size_t)cr1 * 64 + t;

    // ldmatrix per-lane address (logical layout; matches permuted-stored W)
    const int lm_n = ((lane >> 4) & 1) * 8 + (lane & 7);
    const int lm_k = ((lane >> 3) & 1) * 8;
    const uint32_t lmhi = sbase + lm_n * BROW_B + lm_k * 2;

    float acc[8][4];
#pragma unroll
    for (int i = 0; i < 8; i++)
#pragma unroll
        for (int j = 0; j < 4; j++) acc[i][j] = 0.0f;

    // software pipeline: loads for iteration ks are issued in iteration ks-1
    float4 c0 = __ldg(p0);
    float4 c1 = __ldg(p1);

#pragma unroll 1
    for (int ks = 0; ks < 16; ks++) {
        // issue next iteration's loads NOW; consumed after all MMAs below
        float4 n0, n1;
        if (ks < 15) {
            n0 = __ldg(p0 + (ks + 1) * 4);
            n1 = __ldg(p1 + (ks + 1) * 4);
        }

        uint32_t ah[4], al[4];
        CVTHILO2(c0.x, c0.y, ah[0], al[0]);
        CVTHILO2(c1.x, c1.y, ah[1], al[1]);
        CVTHILO2(c0.z, c0.w, ah[2], al[2]);
        CVTHILO2(c1.z, c1.w, ah[3], al[3]);

        // two halves (nt2 pairs) with 8-reg bh cache each; same-acc spacing 4
#pragma unroll
        for (int h = 0; h < 2; h++) {
            uint32_t bh0[4], bh1[4];
            LDM4(bh0, lmhi + (2 * h)     * (16 * BROW_B) + ks * 32);
            LDM4(bh1, lmhi + (2 * h + 1) * (16 * BROW_B) + ks * 32);

            MMA(acc[4 * h],     ah, bh0[0], bh0[1]);   // hi*hi
            MMA(acc[4 * h + 1], ah, bh0[2], bh0[3]);
            MMA(acc[4 * h + 2], ah, bh1[0], bh1[1]);
            MMA(acc[4 * h + 3], ah, bh1[2], bh1[3]);

            MMA(acc[4 * h],     al, bh0[0], bh0[1]);   // lo*hi (reuse bh)
            MMA(acc[4 * h + 1], al, bh0[2], bh0[3]);
            MMA(acc[4 * h + 2], al, bh1[0], bh1[1]);
            MMA(acc[4 * h + 3], al, bh1[2], bh1[3]);

            uint32_t bl0[4], bl1[4];
            LDM4(bl0, lmhi + B_LO_OFF + (2 * h)     * (16 * BROW_B) + ks * 32);
            LDM4(bl1, lmhi + B_LO_OFF + (2 * h + 1) * (16 * BROW_B) + ks * 32);

            MMA(acc[4 * h],     ah, bl0[0], bl0[1]);   // hi*lo
            MMA(acc[4 * h + 1], ah, bl0[2], bl0[3]);
            MMA(acc[4 * h + 2], ah, bl1[0], bl1[1]);
            MMA(acc[4 * h + 3], ah, bl1[2], bl1[3]);
        }

        c0 = n0;
        c1 = n1;
    }

    // ---- epilogue: fully register/shuffle based ----
    const float* sBias = reinterpret_cast<const float*>(smem + BIAS_OFF);
    const float* sWlin = reinterpret_cast<const float*>(smem + WLIN_OFF);
    const float  blin  = reinterpret_cast<const float*>(smem + BLIN_OFF)[0];

#pragma unroll
    for (int row = 0; row < 2; row++) {
        float s = 0.0f;
#pragma unroll
        for (int nt = 0; nt < 4; nt++) {
#pragma unroll
            for (int j = 0; j < 2; j++) {
                int c = nt * 8 + 2 * t + j;
                float zv = acc[nt][row * 2 + j]     + sBias[c];
                float hv = acc[nt + 4][row * 2 + j] + sBias[HID + c];
                float z  = 1.0f / (1.0f + __expf(-zv));
                float th = fast_tanh(hv);
                float h  = fmaxf((1.0f - z) * th, 0.0f);
                s = fmaf(h, sWlin[c], s);
            }
        }
        s += __shfl_xor_sync(0xffffffffu, s, 1);
        s += __shfl_xor_sync(0xffffffffu, s, 2);
        int node = row ? r1 : r0;
        if (t == 0 && node < N_NODES) out[node] = s + blin;
    }
}

extern "C" void kernel_launch(void* const* d_in, const int* in_sizes, int n_in,
                              void* d_out, int out_size)
{
    const float* x    = (const float*)d_in[0];
    const float* Wz   = (const float*)d_in[3];
    const float* bz   = (const float*)d_in[4];
    const float* Wh   = (const float*)d_in[7];
    const float* bh   = (const float*)d_in[8];
    const float* Wlin = (const float*)d_in[9];
    const float* blin = (const float*)d_in[10];
    float* out = (float*)d_out;

    prep_kernel<<<64, 256>>>(Wz, bz, Wh, bh, Wlin, blin);

    cudaFuncSetAttribute(gcn_hmma_kernel,
                         cudaFuncAttributeMaxDynamicSharedMemorySize, SMEM_TOTAL);
    gcn_hmma_kernel<<<NT, 256, SMEM_TOTAL>>>(x, out);
}